// round 8
// baseline (speedup 1.0000x reference)
#include <cuda_runtime.h>
#include <cuda_bf16.h>
#include <cuda_fp16.h>
#include <math.h>

typedef unsigned int u32;
typedef unsigned long long u64;

#define BATCH 2
#define SEQ   2048
#define DIM   512
#define NHEAD 8
#define DK    64
#define MT    (BATCH*SEQ)
#define LOG2E 1.4426950408889634f

// ---------------- global scratch (alloc-free) ------------------------------
__device__ __nv_bfloat16 gXh[MT*DIM], gXl[MT*DIM];
__device__ __nv_bfloat16 gWh[4][DIM*DIM], gWl[4][DIM*DIM];  // 0..2 = QKV (contig), 3 = O
__device__ __half gQ[MT*DIM];                // pre-scaled 0.125*log2e
__device__ __half gK[MT*DIM];
__device__ __half gV[MT*DIM];
__device__ __nv_bfloat16 gOh[MT*DIM], gOl[MT*DIM];
__device__ u32 g_mask[4*SEQ*(SEQ/32)];       // [b*2+par][row][word]

// ---------------- helpers ---------------------------------------------------
static __device__ __forceinline__ u32 smem_u32(const void* p) {
    u32 a; asm("{ .reg .u64 t; cvta.to.shared.u64 t, %1; cvt.u32.u64 %0, t; }" : "=r"(a) : "l"(p));
    return a;
}
static __device__ __forceinline__ float ex2f(float x) {
    float y; asm("ex2.approx.f32 %0, %1;" : "=f"(y) : "f"(x)); return y;
}
static __device__ __forceinline__ void split2(float v, __nv_bfloat16& hi, __nv_bfloat16& lo) {
    hi = __float2bfloat16(v);
    lo = __float2bfloat16(v - __bfloat162float(hi));
}
static __device__ __forceinline__ u32 packbf(__nv_bfloat16 a, __nv_bfloat16 b) {
    return (u32)__bfloat16_as_ushort(a) | ((u32)__bfloat16_as_ushort(b) << 16);
}
// packs {lo, hi} halves
static __device__ __forceinline__ u32 cvtf16x2(float lo, float hi) {
    u32 d; asm("cvt.rn.f16x2.f32 %0, %1, %2;" : "=r"(d) : "f"(hi), "f"(lo)); return d;
}

#define LDM4(r0,r1,r2,r3,a) \
    asm volatile("ldmatrix.sync.aligned.m8n8.x4.shared.b16 {%0,%1,%2,%3}, [%4];" \
        : "=r"(r0),"=r"(r1),"=r"(r2),"=r"(r3) : "r"(a))
#define LDM4T(r0,r1,r2,r3,a) \
    asm volatile("ldmatrix.sync.aligned.m8n8.x4.trans.shared.b16 {%0,%1,%2,%3}, [%4];" \
        : "=r"(r0),"=r"(r1),"=r"(r2),"=r"(r3) : "r"(a))
#define MMAB(d,a,b) \
    asm volatile("mma.sync.aligned.m16n8k16.row.col.f32.bf16.bf16.f32 " \
        "{%0,%1,%2,%3}, {%4,%5,%6,%7}, {%8,%9}, {%0,%1,%2,%3};" \
        : "+f"((d)[0]),"+f"((d)[1]),"+f"((d)[2]),"+f"((d)[3]) \
        : "r"((a)[0]),"r"((a)[1]),"r"((a)[2]),"r"((a)[3]),"r"((b)[0]),"r"((b)[1]))
#define MMAH(d,a,b) \
    asm volatile("mma.sync.aligned.m16n8k16.row.col.f32.f16.f16.f32 " \
        "{%0,%1,%2,%3}, {%4,%5,%6,%7}, {%8,%9}, {%0,%1,%2,%3};" \
        : "+f"((d)[0]),"+f"((d)[1]),"+f"((d)[2]),"+f"((d)[3]) \
        : "r"((a)[0]),"r"((a)[1]),"r"((a)[2]),"r"((a)[3]),"r"((b)[0]),"r"((b)[1]))

#define CPA16(d, s) asm volatile("cp.async.cg.shared.global [%0], [%1], 16;" :: "r"(d), "l"(s) : "memory")
#define CPCOMMIT()  asm volatile("cp.async.commit_group;" ::: "memory")
#define CPWAIT(n)   asm volatile("cp.async.wait_group %0;" :: "n"(n) : "memory")

// ---------------- fp32 -> (hi, lo) bf16 split: x ----------------------------
__global__ void conv_x(const float* __restrict__ src) {
    int i = (blockIdx.x * blockDim.x + threadIdx.x) * 4;
    float4 v = *(const float4*)(src + i);
    __nv_bfloat16 h0,l0,h1,l1,h2,l2,h3,l3;
    split2(v.x,h0,l0); split2(v.y,h1,l1); split2(v.z,h2,l2); split2(v.w,h3,l3);
    *(uint2*)(gXh + i) = make_uint2(packbf(h0,h1), packbf(h2,h3));
    *(uint2*)(gXl + i) = make_uint2(packbf(l0,l1), packbf(l2,l3));
}

// ---------------- fp32 -> (hi, lo) bf16 split: all 4 weights ----------------
__global__ void conv_w(const float* __restrict__ Wq, const float* __restrict__ Wk,
                       const float* __restrict__ Wv, const float* __restrict__ Wo) {
    int sel = blockIdx.x >> 8;               // 256 blocks per weight
    int blk = blockIdx.x & 255;
    const float* src = sel == 0 ? Wq : sel == 1 ? Wk : sel == 2 ? Wv : Wo;
    int i = (blk * blockDim.x + threadIdx.x) * 4;
    float4 v = *(const float4*)(src + i);
    __nv_bfloat16 h0,l0,h1,l1,h2,l2,h3,l3;
    split2(v.x,h0,l0); split2(v.y,h1,l1); split2(v.z,h2,l2); split2(v.w,h3,l3);
    *(uint2*)(gWh[sel] + i) = make_uint2(packbf(h0,h1), packbf(h2,h3));
    *(uint2*)(gWl[sel] + i) = make_uint2(packbf(l0,l1), packbf(l2,l3));
}

// ---------------- combined masks -> bit tables (row per block, batched MLP) -
__global__ void mask_prep(const int* __restrict__ seq_mask,
                          const int* __restrict__ sparse_masks) {
    int row  = blockIdx.x;
    int warp = threadIdx.x >> 5, lane = threadIdx.x & 31;
    const int* s0 = seq_mask     + (size_t)0*SEQ*SEQ + (size_t)row*SEQ;
    const int* s1 = seq_mask     + (size_t)1*SEQ*SEQ + (size_t)row*SEQ;
    const int* p0 = sparse_masks + (size_t)0*SEQ*SEQ + (size_t)row*SEQ;
    const int* p1 = sparse_masks + (size_t)1*SEQ*SEQ + (size_t)row*SEQ;
    int a0[8], a1[8], b0[8], b1[8];
    #pragma unroll
    for (int q = 0; q < 8; q++) {
        int j = (warp*8 + q)*32 + lane;
        a0[q] = s0[j]; a1[q] = s1[j]; b0[q] = p0[j]; b1[q] = p1[j];
    }
    #pragma unroll
    for (int q = 0; q < 8; q++) {
        int w = warp*8 + q;
        u32 m00 = __ballot_sync(0xffffffffu, (a0[q] & b0[q]) != 0);
        u32 m01 = __ballot_sync(0xffffffffu, (a0[q] & b1[q]) != 0);
        u32 m10 = __ballot_sync(0xffffffffu, (a1[q] & b0[q]) != 0);
        u32 m11 = __ballot_sync(0xffffffffu, (a1[q] & b1[q]) != 0);
        if (lane == 0) {
            g_mask[((size_t)0*SEQ + row)*(SEQ/32) + w] = m00;
            g_mask[((size_t)1*SEQ + row)*(SEQ/32) + w] = m01;
            g_mask[((size_t)2*SEQ + row)*(SEQ/32) + w] = m10;
            g_mask[((size_t)3*SEQ + row)*(SEQ/32) + w] = m11;
        }
    }
}

// ---------------- split-bf16 GEMM (mma.sync, 4-stage cp.async, k-chunk 32) --
// mode 0: A = x splits, B = QKV concat [1536][512]; epilogue -> gQ/gK/gV fp16.
// mode 1: A = O splits,  B = Wo [512][512];          epilogue -> fp32 out.
// Stage (24KB): A 64 rows x 128B (hi 64B | lo 64B) @0; B 128 rows x 128B @8192.
#define PJ_STG 24576
__global__ __launch_bounds__(256, 2) void proj_gemm(float* __restrict__ Yout, int mode) {
    extern __shared__ char dsm[];
    u32 sb = (smem_u32(dsm) + 127) & ~127u;

    const __nv_bfloat16* A_h = mode ? gOh : gXh;
    const __nv_bfloat16* A_l = mode ? gOl : gXl;
    const __nv_bfloat16* B_h = mode ? gWh[3] : gWh[0];
    const __nv_bfloat16* B_l = mode ? gWl[3] : gWl[0];

    int tid = threadIdx.x, lane = tid & 31, warp = tid >> 5;
    int t4 = lane & 3, t8 = lane >> 2;
    int mrl = lane & 7, mm = lane >> 3;
    int wm = warp & 1, wn = warp >> 1;            // 2 x 4 warps, warp tile 32x32
    int m0 = blockIdx.x * 64, n0 = blockIdx.y * 128;

    // per stage: 1536 16B-copies (A 512, B 1024); 6 per thread
    #define PJ_ISSUE(c, st) do { \
        _Pragma("unroll") \
        for (int q = 0; q < 6; q++) { \
            int idx = tid + q*256; \
            const __nv_bfloat16* s; u32 d; \
            if (idx < 512) { \
                int r = idx >> 3, ch = idx & 7; \
                s = (ch < 4 ? A_h : A_l) + (size_t)(m0 + r)*DIM + (c)*32 + (ch & 3)*8; \
                d = sb + (st)*PJ_STG + r*128 + ((ch ^ (r & 7)) << 4); \
            } else { \
                int i2 = idx - 512; \
                int r = i2 >> 3, ch = i2 & 7; \
                s = (ch < 4 ? B_h : B_l) + (size_t)(n0 + r)*DIM + (c)*32 + (ch & 3)*8; \
                d = sb + (st)*PJ_STG + 8192 + r*128 + ((ch ^ (r & 7)) << 4); \
            } \
            CPA16(d, s); \
        } \
        CPCOMMIT(); \
    } while (0)

    float C[2][4][4];
    #pragma unroll
    for (int a = 0; a < 2; a++)
        #pragma unroll
        for (int b = 0; b < 4; b++)
            #pragma unroll
            for (int c = 0; c < 4; c++) C[a][b][c] = 0.f;

    PJ_ISSUE(0, 0); PJ_ISSUE(1, 1); PJ_ISSUE(2, 2); PJ_ISSUE(3, 3);

    for (int c = 0; c < 16; c++) {
        if (c <= 12) CPWAIT(3); else if (c == 13) CPWAIT(2);
        else if (c == 14) CPWAIT(1); else CPWAIT(0);
        __syncthreads();
        u32 bb = sb + (c & 3)*PJ_STG;

        #pragma unroll
        for (int ks = 0; ks < 2; ks++) {
            u32 AH[2][4], AL[2][4], BH[4][2], BL[4][2];
            int ch = 2*ks + (mm >> 1);            // 0..3 (hi); lo at ch+4
            #pragma unroll
            for (int fm = 0; fm < 2; fm++) {
                int row = wm*32 + fm*16 + (mm & 1)*8 + mrl;
                u32 aH = bb + row*128 + ((ch ^ (row & 7)) << 4);
                u32 aL = bb + row*128 + (((ch + 4) ^ (row & 7)) << 4);
                LDM4(AH[fm][0], AH[fm][1], AH[fm][2], AH[fm][3], aH);
                LDM4(AL[fm][0], AL[fm][1], AL[fm][2], AL[fm][3], aL);
            }
            #pragma unroll
            for (int p = 0; p < 2; p++) {
                int row = wn*32 + p*16 + (mm & 1)*8 + mrl;
                u32 aH = bb + 8192 + row*128 + ((ch ^ (row & 7)) << 4);
                u32 aL = bb + 8192 + row*128 + (((ch + 4) ^ (row & 7)) << 4);
                LDM4(BH[2*p][0], BH[2*p+1][0], BH[2*p][1], BH[2*p+1][1], aH);
                LDM4(BL[2*p][0], BL[2*p+1][0], BL[2*p][1], BL[2*p+1][1], aL);
            }
            #pragma unroll
            for (int fm = 0; fm < 2; fm++)
                #pragma unroll
                for (int fn = 0; fn < 4; fn++) {
                    MMAB(C[fm][fn], AH[fm], BH[fn]);
                    MMAB(C[fm][fn], AH[fm], BL[fn]);
                    MMAB(C[fm][fn], AL[fm], BH[fn]);
                }
        }
        __syncthreads();
        if (c + 4 < 16) PJ_ISSUE(c + 4, c & 3);
    }

    #pragma unroll
    for (int fm = 0; fm < 2; fm++) {
        int rA = m0 + wm*32 + fm*16 + t8;
        #pragma unroll
        for (int fn = 0; fn < 4; fn++) {
            int n = n0 + wn*32 + fn*8 + 2*t4;
            float c0 = C[fm][fn][0], c1 = C[fm][fn][1];
            float c2 = C[fm][fn][2], c3 = C[fm][fn][3];
            if (mode) {
                *(float2*)(Yout + (size_t)rA*DIM + n)     = make_float2(c0, c1);
                *(float2*)(Yout + (size_t)(rA+8)*DIM + n) = make_float2(c2, c3);
            } else {
                int osel = n >> 9, col = n & 511;
                __half* dst = osel == 0 ? gQ : osel == 1 ? gK : gV;
                float sc = osel == 0 ? 0.125f * LOG2E : 1.f;
                *(u32*)(dst + (size_t)rA*DIM + col)     = cvtf16x2(c0*sc, c1*sc);
                *(u32*)(dst + (size_t)(rA+8)*DIM + col) = cvtf16x2(c2*sc, c3*sc);
            }
        }
    }
}

// ---------------- flash attention (fp16 mma, j-tile 128, 3-stage) -----------
// CTA: 128 i-rows of one (b,h); 8 warps x 16 rows; 16 j-tiles of 128
// (processed as two independent 64-j half-chains per iteration).
#define AT_STG 32768   // per stage: K 16KB @0 (128 rows x 128B), V 16KB @16384
__global__ __launch_bounds__(256, 2) void attn_kernel() {
    extern __shared__ char dsm[];
    u32 sb = (smem_u32(dsm) + 127) & ~127u;

    int tid = threadIdx.x, lane = tid & 31, warp = tid >> 5;
    int t4 = lane & 3, t8 = lane >> 2;
    int mrl = lane & 7, mm = lane >> 3;
    int i0 = blockIdx.x * 128;
    int bh = blockIdx.y, b = bh >> 3, hh = bh & 7;
    int combo = b*2 + (hh & 1);

    // per stage: 2048 16B-copies (K 1024, V 1024); 8 per thread
    #define AT_ISSUE(jt, st) do { \
        _Pragma("unroll") \
        for (int q = 0; q < 8; q++) { \
            int idx = tid + q*256; \
            int mtx = idx >> 10, rem = idx & 1023, r = rem >> 3, ch = rem & 7; \
            const __half* s = (mtx ? gV : gK) + (size_t)(b*SEQ + (jt)*128 + r)*DIM + hh*DK + ch*8; \
            u32 d = sb + (st)*AT_STG + mtx*16384 + r*128 + ((ch ^ (r & 7)) << 4); \
            CPA16(d, s); \
        } \
        CPCOMMIT(); \
    } while (0)

    AT_ISSUE(0, 0);
    AT_ISSUE(1, 1);
    AT_ISSUE(2, 2);

    // Q fragments (fp16) held in registers for the whole kernel
    u32 QA[4][4];
    {
        size_t qbase = (size_t)(b*SEQ + i0 + warp*16 + t8)*DIM + hh*DK + 2*t4;
        #pragma unroll
        for (int ks = 0; ks < 4; ks++) {
            QA[ks][0] = *(const u32*)(gQ + qbase + ks*16);
            QA[ks][1] = *(const u32*)(gQ + qbase + ks*16 + 8*DIM);
            QA[ks][2] = *(const u32*)(gQ + qbase + ks*16 + 8);
            QA[ks][3] = *(const u32*)(gQ + qbase + ks*16 + 8*DIM + 8);
        }
    }

    const u32* mrowA = g_mask + ((size_t)combo*SEQ + i0 + warp*16 + t8)*(SEQ/32);
    const u32* mrowB = mrowA + 8*(SEQ/32);

    float O[8][4];
    #pragma unroll
    for (int f = 0; f < 8; f++)
        #pragma unroll
        for (int c = 0; c < 4; c++) O[f][c] = 0.f;
    float lsA = 0.f, lsB = 0.f;

    int stage = 0;
    for (int t = 0; t < 16; t++) {
        if (t <= 13) CPWAIT(2); else if (t == 14) CPWAIT(1); else CPWAIT(0);
        __syncthreads();
        u32 kb = sb + stage*AT_STG;
        u32 vb = kb + 16384;

        // mask words for both halves (LDG hidden under MMAs)
        uint4 mA = *(const uint4*)(mrowA + (t << 2));
        uint4 mB = *(const uint4*)(mrowB + (t << 2));

        #pragma unroll
        for (int h = 0; h < 2; h++) {
            // S = Q K^T over this 64-j half
            float S[8][4];
            #pragma unroll
            for (int f = 0; f < 8; f++)
                #pragma unroll
                for (int c = 0; c < 4; c++) S[f][c] = 0.f;

            #pragma unroll
            for (int ks = 0; ks < 4; ks++) {
                u32 BH[8][2];
                int ch = 2*ks + (mm >> 1);
                #pragma unroll
                for (int p = 0; p < 4; p++) {
                    int row = h*64 + 16*p + (mm & 1)*8 + mrl;
                    u32 a = kb + row*128 + ((ch ^ (row & 7)) << 4);
                    LDM4(BH[2*p][0], BH[2*p+1][0], BH[2*p][1], BH[2*p+1][1], a);
                }
                #pragma unroll
                for (int f = 0; f < 8; f++) MMAH(S[f], QA[ks], BH[f]);
            }

            u64 mwA = h ? ((u64)mA.z | ((u64)mA.w << 32)) : ((u64)mA.x | ((u64)mA.y << 32));
            u64 mwB = h ? ((u64)mB.z | ((u64)mB.w << 32)) : ((u64)mB.x | ((u64)mB.y << 32));

            u32 PH[4][4];
            #pragma unroll
            for (int f = 0; f < 8; f++) {
                int sh = 8*f + 2*t4;
                u32 bA = (u32)(mwA >> sh);
                u32 bB = (u32)(mwB >> sh);
                float p0 = (bA & 1u) ? ex2f(S[f][0]) : 0.f;
                float p1 = (bA & 2u) ? ex2f(S[f][1]) : 0.f;
                float p2 = (bB & 1u) ? ex2f(S[f][2]) : 0.f;
                float p3 = (bB & 2u) ? ex2f(S[f][3]) : 0.f;
                lsA += p0 + p1;
                lsB += p2 + p3;
                int ks = f >> 1, o = (f & 1)*2;
                PH[ks][o]   = cvtf16x2(p0, p1);
                PH[ks][o+1] = cvtf16x2(p2, p3);
            }

            // O += P V  (V fragments via ldmatrix.trans)
            #pragma unroll
            for (int ks = 0; ks < 4; ks++) {
                u32 VH[8][2];
                int row = h*64 + 16*ks + (mm >> 1)*8 + mrl;
                #pragma unroll
                for (int p = 0; p < 4; p++) {
                    int ch = 2*p + (mm & 1);
                    u32 a = vb + row*128 + ((ch ^ (row & 7)) << 4);
                    LDM4T(VH[2*p][0], VH[2*p+1][0], VH[2*p][1], VH[2*p+1][1], a);
                }
                #pragma unroll
                for (int f = 0; f < 8; f++) MMAH(O[f], PH[ks], VH[f]);
            }
        }
        __syncthreads();
        if (t + 3 < 16) AT_ISSUE(t + 3, stage);
        stage = (stage == 2) ? 0 : stage + 1;
    }

    // reduce row sums across the 4 lanes sharing each row, normalize, store
    lsA += __shfl_xor_sync(0xffffffffu, lsA, 1);
    lsA += __shfl_xor_sync(0xffffffffu, lsA, 2);
    lsB += __shfl_xor_sync(0xffffffffu, lsB, 1);
    lsB += __shfl_xor_sync(0xffffffffu, lsB, 2);
    float invA = (lsA > 0.f) ? 1.0f / lsA : 0.f;
    float invB = (lsB > 0.f) ? 1.0f / lsB : 0.f;

    size_t obase = (size_t)(b*SEQ + i0 + warp*16 + t8)*DIM + hh*DK + 2*t4;
    #pragma unroll
    for (int f = 0; f < 8; f++) {
        float o0 = O[f][0]*invA, o1 = O[f][1]*invA;
        float o2 = O[f][2]*invB, o3 = O[f][3]*invB;
        __nv_bfloat16 h0,l0,h1,l1,h2,l2,h3,l3;
        split2(o0,h0,l0); split2(o1,h1,l1); split2(o2,h2,l2); split2(o3,h3,l3);
        *(u32*)(gOh + obase + 8*f)         = packbf(h0, h1);
        *(u32*)(gOl + obase + 8*f)         = packbf(l0, l1);
        *(u32*)(gOh + obase + 8*f + 8*DIM) = packbf(h2, h3);
        *(u32*)(gOl + obase + 8*f + 8*DIM) = packbf(l2, l3);
    }
}

// ---------------------------------------------------------------------------
extern "C" void kernel_launch(void* const* d_in, const int* in_sizes, int n_in,
                              void* d_out, int out_size)
{
    const float* x  = (const float*)d_in[0];
    const float* Wq = (const float*)d_in[1];
    const float* Wk = (const float*)d_in[2];
    const float* Wv = (const float*)d_in[3];
    const float* Wo = (const float*)d_in[4];
    const int* seq_mask     = (const int*)d_in[5];
    const int* sparse_masks = (const int*)d_in[6];
    float* out = (float*)d_out;

    cudaFuncSetAttribute(proj_gemm,   cudaFuncAttributeMaxDynamicSharedMemorySize, 4*PJ_STG);
    cudaFuncSetAttribute(attn_kernel, cudaFuncAttributeMaxDynamicSharedMemorySize, 3*AT_STG);

    mask_prep<<<SEQ, 256>>>(seq_mask, sparse_masks);
    conv_x<<<MT*DIM/1024, 256>>>(x);
    conv_w<<<4*DIM*DIM/1024, 256>>>(Wq, Wk, Wv, Wo);

    proj_gemm<<<dim3(MT/64, 1536/128), 256, 4*PJ_STG>>>(nullptr, 0); // fused QKV
    attn_kernel<<<dim3(SEQ/128, BATCH*NHEAD), 256, 3*AT_STG>>>();
    proj_gemm<<<dim3(MT/64, DIM/128), 256, 4*PJ_STG>>>(out, 1);      // O @ Wo^T
    (void)in_sizes; (void)n_in; (void)out_size;
}